// round 1
// baseline (speedup 1.0000x reference)
#include <cuda_runtime.h>
#include <math.h>

#define BATCH 128
#define KK    512
#define JCH   4      // column chunks per batch
#define TPB   128    // threads per block (one column per thread)

// log(512)
#define LOGK 6.2383246250395077632f

// Scratch (allocation-free rule: __device__ globals). Fully overwritten each launch.
__device__ float g_E0[BATCH * KK];          // sum_i exp(logQ0[b,i,j])
__device__ float g_E1[BATCH * KK];          // sum_i exp(logQ1[b,i,j])
__device__ float g_partial[BATCH * JCH];    // per-(b,chunk) partial sums of t[b,j]

// ---------------------------------------------------------------------------
// Kernel 1: column sums of exp() for logQ0 and logQ1.
// grid = (JCH, BATCH, 2), block = TPB. Thread owns one column j; streams 512
// rows (stride K floats) -> warp reads one contiguous 128B line per row.
// ---------------------------------------------------------------------------
__global__ void __launch_bounds__(TPB) k_colsum(const float* __restrict__ Q0,
                                                const float* __restrict__ Q1)
{
    const int j = blockIdx.x * TPB + threadIdx.x;
    const int b = blockIdx.y;
    const float* __restrict__ src = blockIdx.z ? Q1 : Q0;
    float* dst = blockIdx.z ? g_E1 : g_E0;

    const float* p = src + (size_t)b * KK * KK + j;

    float s0 = 0.f, s1 = 0.f, s2 = 0.f, s3 = 0.f;
#pragma unroll 2
    for (int i = 0; i < KK; i += 4) {
        float a0 = p[(size_t)(i + 0) * KK];
        float a1 = p[(size_t)(i + 1) * KK];
        float a2 = p[(size_t)(i + 2) * KK];
        float a3 = p[(size_t)(i + 3) * KK];
        s0 += __expf(a0);
        s1 += __expf(a1);
        s2 += __expf(a2);
        s3 += __expf(a3);
    }
    dst[b * KK + j] = (s0 + s1) + (s2 + s3);
}

// ---------------------------------------------------------------------------
// Kernel 2: mm[b,j] = sum_i ew[b,i] * exp(logP1[b,i,j]);
//           t[b,j]  = mm/E0 * exp(logP2[b,j]); partial-sum t over the chunk.
// grid = (JCH, BATCH), block = TPB.
// ---------------------------------------------------------------------------
__global__ void __launch_bounds__(TPB) k_mid(const float* __restrict__ P0,
                                             const float* __restrict__ P1,
                                             const float* __restrict__ P2)
{
    const int b = blockIdx.y;
    const int j = blockIdx.x * TPB + threadIdx.x;

    __shared__ float ew[KK];
    for (int i = threadIdx.x; i < KK; i += TPB) {
        // ew[i] = exp(logP0[b,i]) * K / E1[b,i]
        ew[i] = __expf(P0[b * KK + i]) * (float)KK / g_E1[b * KK + i];
    }
    __syncthreads();

    const float* p = P1 + (size_t)b * KK * KK + j;

    float s0 = 0.f, s1 = 0.f, s2 = 0.f, s3 = 0.f;
#pragma unroll 2
    for (int i = 0; i < KK; i += 4) {
        float a0 = p[(size_t)(i + 0) * KK];
        float a1 = p[(size_t)(i + 1) * KK];
        float a2 = p[(size_t)(i + 2) * KK];
        float a3 = p[(size_t)(i + 3) * KK];
        s0 += ew[i + 0] * __expf(a0);   // ew broadcast from smem (conflict-free)
        s1 += ew[i + 1] * __expf(a1);
        s2 += ew[i + 2] * __expf(a2);
        s3 += ew[i + 3] * __expf(a3);
    }
    float mm = (s0 + s1) + (s2 + s3);
    float t  = mm / g_E0[b * KK + j] * __expf(P2[b * KK + j]);

    // Deterministic block reduction of t over TPB threads.
    float v = t;
#pragma unroll
    for (int o = 16; o; o >>= 1)
        v += __shfl_down_sync(0xFFFFFFFFu, v, o);

    __shared__ float red[TPB / 32];
    if ((threadIdx.x & 31) == 0) red[threadIdx.x >> 5] = v;
    __syncthreads();
    if (threadIdx.x == 0) {
        float r = (red[0] + red[1]) + (red[2] + red[3]);
        g_partial[b * JCH + blockIdx.x] = r;
    }
}

// ---------------------------------------------------------------------------
// Kernel 3: P_obj = sum_b (logK - log(sum_j t[b,j])). Deterministic tree sum.
// ---------------------------------------------------------------------------
__global__ void __launch_bounds__(BATCH) k_final(float* __restrict__ out)
{
    const int b = threadIdx.x;  // one thread per batch
    float s = (g_partial[b * JCH + 0] + g_partial[b * JCH + 1]) +
              (g_partial[b * JCH + 2] + g_partial[b * JCH + 3]);
    float val = LOGK - logf(s);

    __shared__ float sm[BATCH];
    sm[b] = val;
    __syncthreads();
#pragma unroll
    for (int off = BATCH / 2; off > 0; off >>= 1) {
        if (b < off) sm[b] += sm[b + off];
        __syncthreads();
    }
    if (b == 0) out[0] = sm[0];
}

// ---------------------------------------------------------------------------
extern "C" void kernel_launch(void* const* d_in, const int* in_sizes, int n_in,
                              void* d_out, int out_size)
{
    const float* Q0 = (const float*)d_in[0];  // logQ0 [B,K,K]
    const float* Q1 = (const float*)d_in[1];  // logQ1 [B,K,K]
    const float* P0 = (const float*)d_in[2];  // logP0 [B,1,K]
    const float* P1 = (const float*)d_in[3];  // logP1 [B,K,K]
    const float* P2 = (const float*)d_in[4];  // logP2 [B,K,1]

    dim3 g1(JCH, BATCH, 2);
    k_colsum<<<g1, TPB>>>(Q0, Q1);

    dim3 g2(JCH, BATCH);
    k_mid<<<g2, TPB>>>(P0, P1, P2);

    k_final<<<1, BATCH>>>((float*)d_out);
}

// round 2
// speedup vs baseline: 1.3374x; 1.3374x over previous
#include <cuda_runtime.h>
#include <math.h>

#define BATCH  128
#define KK     512
#define JCH    4      // column chunks of 128 per batch row-block
#define ISPL   4      // i-dimension splits (128 rows each)
#define TPB    128

#define LOGK 6.2383246250395077632f   // log(512)

// Scratch (__device__ globals; allocation-free rule). Fully overwritten per launch.
__device__ float g_Ep[2 * ISPL * BATCH * KK];   // partial col-sums for Q0/Q1 (2 MB)
__device__ float g_ew[BATCH * KK];              // exp(P0)*K/E1
__device__ float g_E0inv[BATCH * KK];           // 1/E0
__device__ float g_mmp[ISPL * BATCH * KK];      // partial mm sums (1 MB)
__device__ float g_sb[BATCH];                   // per-batch logK - log(sum_j t)

// ---------------------------------------------------------------------------
// Kernel 1: partial column sums of exp() for Q0 and Q1.
// grid = (JCH, BATCH, 2*ISPL), block = 128. Each block: 128 rows x 128 cols.
// ---------------------------------------------------------------------------
__global__ void __launch_bounds__(TPB) k_colsum(const float* __restrict__ Q0,
                                                const float* __restrict__ Q1)
{
    const int j     = blockIdx.x * TPB + threadIdx.x;
    const int b     = blockIdx.y;
    const int which = blockIdx.z >> 2;      // 0 -> Q0, 1 -> Q1
    const int slice = blockIdx.z & 3;       // i slice

    const float* __restrict__ src = which ? Q1 : Q0;
    const float* p = src + (size_t)b * KK * KK + (size_t)(slice * 128) * KK + j;

    float s0 = 0.f, s1 = 0.f, s2 = 0.f, s3 = 0.f;
    for (int i = 0; i < 128; i += 8) {
        float a0 = p[(size_t)(i + 0) * KK];
        float a1 = p[(size_t)(i + 1) * KK];
        float a2 = p[(size_t)(i + 2) * KK];
        float a3 = p[(size_t)(i + 3) * KK];
        float a4 = p[(size_t)(i + 4) * KK];
        float a5 = p[(size_t)(i + 5) * KK];
        float a6 = p[(size_t)(i + 6) * KK];
        float a7 = p[(size_t)(i + 7) * KK];
        s0 += __expf(a0); s1 += __expf(a1);
        s2 += __expf(a2); s3 += __expf(a3);
        s0 += __expf(a4); s1 += __expf(a5);
        s2 += __expf(a6); s3 += __expf(a7);
    }
    g_Ep[((which * ISPL + slice) * BATCH + b) * KK + j] = (s0 + s1) + (s2 + s3);
}

// ---------------------------------------------------------------------------
// Kernel 2: combine partials -> ew[b,i] = exp(P0)*K/E1,  E0inv[b,j] = 1/E0.
// grid = BATCH, block = 512 (one thread per column index).
// ---------------------------------------------------------------------------
__global__ void __launch_bounds__(512) k_combine(const float* __restrict__ P0)
{
    const int b = blockIdx.x;
    const int j = threadIdx.x;
    const int base = b * KK + j;

    float e0 = 0.f, e1 = 0.f;
#pragma unroll
    for (int s = 0; s < ISPL; s++) {
        e0 += g_Ep[((0 * ISPL + s) * BATCH + b) * KK + j];
        e1 += g_Ep[((1 * ISPL + s) * BATCH + b) * KK + j];
    }
    g_E0inv[base] = 1.0f / e0;
    g_ew[base]    = __expf(P0[base]) * (float)KK / e1;
}

// ---------------------------------------------------------------------------
// Kernel 3: partial mm[b,j] = sum_{i in slice} ew[b,i] * exp(P1[b,i,j]).
// grid = (JCH, BATCH, ISPL), block = 128.
// ---------------------------------------------------------------------------
__global__ void __launch_bounds__(TPB) k_mid(const float* __restrict__ P1)
{
    const int j     = blockIdx.x * TPB + threadIdx.x;
    const int b     = blockIdx.y;
    const int slice = blockIdx.z;
    const int i0    = slice * 128;

    __shared__ float ew[128];
    ew[threadIdx.x] = g_ew[b * KK + i0 + threadIdx.x];
    __syncthreads();

    const float* p = P1 + (size_t)b * KK * KK + (size_t)i0 * KK + j;

    float s0 = 0.f, s1 = 0.f, s2 = 0.f, s3 = 0.f;
    for (int i = 0; i < 128; i += 8) {
        float a0 = p[(size_t)(i + 0) * KK];
        float a1 = p[(size_t)(i + 1) * KK];
        float a2 = p[(size_t)(i + 2) * KK];
        float a3 = p[(size_t)(i + 3) * KK];
        float a4 = p[(size_t)(i + 4) * KK];
        float a5 = p[(size_t)(i + 5) * KK];
        float a6 = p[(size_t)(i + 6) * KK];
        float a7 = p[(size_t)(i + 7) * KK];
        s0 += ew[i + 0] * __expf(a0);
        s1 += ew[i + 1] * __expf(a1);
        s2 += ew[i + 2] * __expf(a2);
        s3 += ew[i + 3] * __expf(a3);
        s0 += ew[i + 4] * __expf(a4);
        s1 += ew[i + 5] * __expf(a5);
        s2 += ew[i + 6] * __expf(a6);
        s3 += ew[i + 7] * __expf(a7);
    }
    g_mmp[(slice * BATCH + b) * KK + j] = (s0 + s1) + (s2 + s3);
}

// ---------------------------------------------------------------------------
// Kernel 4: per-batch s[b] = sum_j (sum_s mmp) * E0inv * exp(P2);
//           g_sb[b] = logK - log(s[b]).   grid = BATCH, block = 128.
// ---------------------------------------------------------------------------
__global__ void __launch_bounds__(TPB) k_finalA(const float* __restrict__ P2)
{
    const int b = blockIdx.x;
    const int t = threadIdx.x;

    float acc = 0.f;
#pragma unroll
    for (int jj = 0; jj < 4; jj++) {
        const int j = jj * TPB + t;
        float m = 0.f;
#pragma unroll
        for (int s = 0; s < ISPL; s++)
            m += g_mmp[(s * BATCH + b) * KK + j];
        acc += m * g_E0inv[b * KK + j] * __expf(P2[b * KK + j]);
    }

    // deterministic block reduction
#pragma unroll
    for (int o = 16; o; o >>= 1)
        acc += __shfl_down_sync(0xFFFFFFFFu, acc, o);

    __shared__ float red[TPB / 32];
    if ((t & 31) == 0) red[t >> 5] = acc;
    __syncthreads();
    if (t == 0) {
        float r = (red[0] + red[1]) + (red[2] + red[3]);
        g_sb[b] = LOGK - logf(r);
    }
}

// ---------------------------------------------------------------------------
// Kernel 5: scalar output = sum_b g_sb[b]. Deterministic tree sum.
// ---------------------------------------------------------------------------
__global__ void __launch_bounds__(BATCH) k_finalB(float* __restrict__ out)
{
    const int b = threadIdx.x;
    __shared__ float sm[BATCH];
    sm[b] = g_sb[b];
    __syncthreads();
#pragma unroll
    for (int off = BATCH / 2; off > 0; off >>= 1) {
        if (b < off) sm[b] += sm[b + off];
        __syncthreads();
    }
    if (b == 0) out[0] = sm[0];
}

// ---------------------------------------------------------------------------
extern "C" void kernel_launch(void* const* d_in, const int* in_sizes, int n_in,
                              void* d_out, int out_size)
{
    const float* Q0 = (const float*)d_in[0];  // logQ0 [B,K,K]
    const float* Q1 = (const float*)d_in[1];  // logQ1 [B,K,K]
    const float* P0 = (const float*)d_in[2];  // logP0 [B,1,K]
    const float* P1 = (const float*)d_in[3];  // logP1 [B,K,K]
    const float* P2 = (const float*)d_in[4];  // logP2 [B,K,1]

    dim3 g1(JCH, BATCH, 2 * ISPL);
    k_colsum<<<g1, TPB>>>(Q0, Q1);

    k_combine<<<BATCH, 512>>>(P0);

    dim3 g3(JCH, BATCH, ISPL);
    k_mid<<<g3, TPB>>>(P1);

    k_finalA<<<BATCH, TPB>>>(P2);
    k_finalB<<<1, BATCH>>>((float*)d_out);
}